// round 2
// baseline (speedup 1.0000x reference)
#include <cuda_runtime.h>
#include <cuda_bf16.h>
#include <cstdint>

#define NNODES 100000
#define NEDGES 1000000
#define HDIM   64
#define ODIM   16
#define NREL   90
#define NBASES 8
#define KDIM   512   // NBASES*HDIM

// ---------------- scratch (device globals; no allocations allowed) ----------
__device__ __align__(16) float g_agg[(size_t)NNODES * KDIM];   // ~205 MB
__device__ __align__(16) float g_h[(size_t)NNODES * HDIM];     // hidden activations
__device__ int g_deg[NNODES];
__device__ int g_cursor[NNODES];
__device__ int g_rowptr[NNODES + 1];
__device__ unsigned long long g_packed[NEDGES];                // (norm<<32)|(etype<<17)|src
__device__ __align__(16) __nv_bfloat16 g_Whi[3][KDIM * 64];    // padded to 64 cols
__device__ __align__(16) __nv_bfloat16 g_Wlo[3][KDIM * 64];

// ---------------- preprocessing kernels -------------------------------------
__global__ void zero_kernel() {
    int i = blockIdx.x * blockDim.x + threadIdx.x;
    if (i < NNODES) { g_deg[i] = 0; g_cursor[i] = 0; }
}

__global__ void hist_kernel(const int* __restrict__ dst) {
    int i = blockIdx.x * blockDim.x + threadIdx.x;
    if (i < NEDGES) atomicAdd(&g_deg[dst[i]], 1);
}

__global__ void scan_kernel() {
    __shared__ int wsum[32];
    __shared__ int carry;
    int t = threadIdx.x;
    if (t == 0) carry = 0;
    __syncthreads();
    for (int base = 0; base < NNODES; base += 1024) {
        int i = base + t;
        int v = (i < NNODES) ? g_deg[i] : 0;
        int x = v;
        #pragma unroll
        for (int o = 1; o < 32; o <<= 1) {
            int y = __shfl_up_sync(0xffffffffu, x, o);
            if ((t & 31) >= o) x += y;
        }
        if ((t & 31) == 31) wsum[t >> 5] = x;
        __syncthreads();
        if (t < 32) {
            int s = wsum[t];
            #pragma unroll
            for (int o = 1; o < 32; o <<= 1) {
                int y = __shfl_up_sync(0xffffffffu, s, o);
                if (t >= o) s += y;
            }
            wsum[t] = s;
        }
        __syncthreads();
        int pre = (t >= 32) ? wsum[(t >> 5) - 1] : 0;
        int incl = x + pre;
        if (i < NNODES) g_rowptr[i] = carry + incl - v;   // exclusive
        int total = wsum[31];
        __syncthreads();
        if (t == 0) carry += total;
        __syncthreads();
    }
    if (t == 0) g_rowptr[NNODES] = carry;
}

__global__ void scatter_kernel(const int* __restrict__ src, const int* __restrict__ dst,
                               const int* __restrict__ etype, const float* __restrict__ norm) {
    int i = blockIdx.x * blockDim.x + threadIdx.x;
    if (i >= NEDGES) return;
    int d = dst[i];
    int pos = g_rowptr[d] + atomicAdd(&g_cursor[d], 1);
    unsigned lo = (unsigned)src[i] | ((unsigned)etype[i] << 17);
    g_packed[pos] = ((unsigned long long)__float_as_uint(norm[i]) << 32) | (unsigned long long)lo;
}

// Convert layer weight matrices to bf16 hi/lo split, padded to 64 output cols.
__global__ void wconv_kernel(const float* __restrict__ b0, const float* __restrict__ b1,
                             const float* __restrict__ b2) {
    int i = blockIdx.x * blockDim.x + threadIdx.x;
    if (i >= 3 * KDIM * 64) return;
    int layer = i / (KDIM * 64);
    int r = i % (KDIM * 64);
    int k = r >> 6, j = r & 63;
    float v;
    if (layer == 0)      v = b0[k * 64 + j];
    else if (layer == 1) v = b1[k * 64 + j];
    else                 v = (j < ODIM) ? b2[k * ODIM + j] : 0.0f;
    __nv_bfloat16 hi = __float2bfloat16(v);
    __nv_bfloat16 lo = __float2bfloat16(v - __bfloat162float(hi));
    g_Whi[layer][r] = hi;
    g_Wlo[layer][r] = lo;
}

// ---------------- aggregation: agg[d,b,i] = sum_e w_eb * x[src_e,i] ---------
__global__ void agg_kernel(const float* __restrict__ xin, const float* __restrict__ coeff) {
    __shared__ float cs[NREL * NBASES];
    const float* x = xin ? xin : g_h;
    for (int i = threadIdx.x; i < NREL * NBASES; i += blockDim.x) cs[i] = coeff[i];
    __syncthreads();
    int w = (blockIdx.x * blockDim.x + threadIdx.x) >> 5;
    int lane = threadIdx.x & 31;
    if (w >= NNODES) return;
    int s = g_rowptr[w], e = g_rowptr[w + 1];
    float acc[16];
    #pragma unroll
    for (int k = 0; k < 16; k++) acc[k] = 0.0f;
    for (int i = s; i < e; i++) {
        unsigned long long p = __ldg(&g_packed[i]);
        unsigned lo = (unsigned)p;
        int srcn = lo & 0x1FFFF;
        int rel = (lo >> 17) & 0x7F;
        float nrm = __uint_as_float((unsigned)(p >> 32));
        float xa = __ldg(&x[(size_t)srcn * 64 + lane]);
        float xb = __ldg(&x[(size_t)srcn * 64 + 32 + lane]);
        const float* c = &cs[rel * 8];
        #pragma unroll
        for (int b = 0; b < 8; b++) {
            float wt = nrm * c[b];
            acc[2 * b]     += wt * xa;
            acc[2 * b + 1] += wt * xb;
        }
    }
    float* o = g_agg + (size_t)w * KDIM;
    #pragma unroll
    for (int b = 0; b < 8; b++) {
        o[b * 64 + lane]      = acc[2 * b];
        o[b * 64 + 32 + lane] = acc[2 * b + 1];
    }
}

// ---------------- GEMM: out = act(agg[N,512] @ W[512,64] + bias) ------------
__device__ __forceinline__ uint32_t swz(uint32_t o) { return o ^ ((o >> 3) & 0x70); }

__device__ __forceinline__ uint32_t pack2(__nv_bfloat16 a, __nv_bfloat16 b) {
    __nv_bfloat162 t = __halves2bfloat162(a, b);
    return *reinterpret_cast<uint32_t*>(&t);
}

__device__ __forceinline__ void ldsm4(uint32_t* r, uint32_t addr) {
    asm volatile("ldmatrix.sync.aligned.m8n8.x4.shared.b16 {%0,%1,%2,%3}, [%4];"
                 : "=r"(r[0]), "=r"(r[1]), "=r"(r[2]), "=r"(r[3]) : "r"(addr));
}
__device__ __forceinline__ void ldsm4t(uint32_t* r, uint32_t addr) {
    asm volatile("ldmatrix.sync.aligned.m8n8.x4.trans.shared.b16 {%0,%1,%2,%3}, [%4];"
                 : "=r"(r[0]), "=r"(r[1]), "=r"(r[2]), "=r"(r[3]) : "r"(addr));
}
__device__ __forceinline__ void mma16816(float* d, const uint32_t* a, const uint32_t* b) {
    asm volatile("mma.sync.aligned.m16n8k16.row.col.f32.bf16.bf16.f32 "
                 "{%0,%1,%2,%3}, {%4,%5,%6,%7}, {%8,%9}, {%0,%1,%2,%3};"
                 : "+f"(d[0]), "+f"(d[1]), "+f"(d[2]), "+f"(d[3])
                 : "r"(a[0]), "r"(a[1]), "r"(a[2]), "r"(a[3]), "r"(b[0]), "r"(b[1]));
}

template <bool RELU, int OCOLS>
__global__ void __launch_bounds__(256) gemm_kernel(int layer, const float* __restrict__ bias,
                                                   float* __restrict__ outp) {
    __shared__ __nv_bfloat16 sAh[128 * 64];
    __shared__ __nv_bfloat16 sAl[128 * 64];
    __shared__ __nv_bfloat16 sBh[64 * 64];
    __shared__ __nv_bfloat16 sBl[64 * 64];

    const float* A = g_agg;
    const __nv_bfloat16* Whi = g_Whi[layer];
    const __nv_bfloat16* Wlo = g_Wlo[layer];
    float* out = outp ? outp : g_h;

    uint32_t uAh = (uint32_t)__cvta_generic_to_shared(sAh);
    uint32_t uAl = (uint32_t)__cvta_generic_to_shared(sAl);
    uint32_t uBh = (uint32_t)__cvta_generic_to_shared(sBh);
    uint32_t uBl = (uint32_t)__cvta_generic_to_shared(sBl);

    int tid = threadIdx.x;
    int wid = tid >> 5, lane = tid & 31;
    int wm = wid & 3, wn = wid >> 2;
    int blockRow = blockIdx.x * 128;

    float acc[2][4][4];
    #pragma unroll
    for (int a = 0; a < 2; a++)
        #pragma unroll
        for (int b = 0; b < 4; b++)
            #pragma unroll
            for (int c = 0; c < 4; c++) acc[a][b][c] = 0.0f;

    for (int kc = 0; kc < KDIM; kc += 64) {
        // Load A chunk [128 rows x 64 k] fp32 -> bf16 hi/lo into swizzled smem.
        #pragma unroll
        for (int it = 0; it < 8; it++) {
            int f = it * 256 + tid;          // float4 index: 16 per row
            int row = f >> 4, c4 = f & 15;
            int gr = blockRow + row;
            float4 v = make_float4(0.f, 0.f, 0.f, 0.f);
            if (gr < NNODES)
                v = *reinterpret_cast<const float4*>(A + (size_t)gr * KDIM + kc + c4 * 4);
            __nv_bfloat16 h0 = __float2bfloat16(v.x), h1 = __float2bfloat16(v.y);
            __nv_bfloat16 h2 = __float2bfloat16(v.z), h3 = __float2bfloat16(v.w);
            __nv_bfloat16 l0 = __float2bfloat16(v.x - __bfloat162float(h0));
            __nv_bfloat16 l1 = __float2bfloat16(v.y - __bfloat162float(h1));
            __nv_bfloat16 l2 = __float2bfloat16(v.z - __bfloat162float(h2));
            __nv_bfloat16 l3 = __float2bfloat16(v.w - __bfloat162float(h3));
            uint32_t o = swz((uint32_t)(row * 128 + c4 * 8));
            *reinterpret_cast<uint2*>(reinterpret_cast<char*>(sAh) + o) =
                make_uint2(pack2(h0, h1), pack2(h2, h3));
            *reinterpret_cast<uint2*>(reinterpret_cast<char*>(sAl) + o) =
                make_uint2(pack2(l0, l1), pack2(l2, l3));
        }
        // Load B chunk [64 k x 64 n] bf16 into swizzled smem (hi and lo).
        #pragma unroll
        for (int it = 0; it < 2; it++) {
            int u = it * 256 + tid;          // 16B units: 8 per row
            int row = u >> 3, g = u & 7;
            uint32_t o = swz((uint32_t)(row * 128 + g * 16));
            *reinterpret_cast<uint4*>(reinterpret_cast<char*>(sBh) + o) =
                *reinterpret_cast<const uint4*>(reinterpret_cast<const char*>(Whi) +
                                                (size_t)(kc + row) * 128 + g * 16);
            *reinterpret_cast<uint4*>(reinterpret_cast<char*>(sBl) + o) =
                *reinterpret_cast<const uint4*>(reinterpret_cast<const char*>(Wlo) +
                                                (size_t)(kc + row) * 128 + g * 16);
        }
        __syncthreads();

        #pragma unroll
        for (int ks = 0; ks < 4; ks++) {
            uint32_t ah[2][4], al[2][4], bh[2][4], bl[2][4];
            #pragma unroll
            for (int mt = 0; mt < 2; mt++) {
                int r = wm * 32 + mt * 16 + (lane & 15);
                uint32_t o = swz((uint32_t)(r * 128 + ks * 32 + (lane >> 4) * 16));
                ldsm4(ah[mt], uAh + o);
                ldsm4(al[mt], uAl + o);
            }
            #pragma unroll
            for (int p = 0; p < 2; p++) {
                int mat = lane >> 3, sub = lane & 7;
                int krow = ks * 16 + (mat & 1) * 8 + sub;
                int nb = wn * 32 + p * 16 + (mat >> 1) * 8;
                uint32_t o = swz((uint32_t)(krow * 128 + nb * 2));
                ldsm4t(bh[p], uBh + o);
                ldsm4t(bl[p], uBl + o);
            }
            #pragma unroll
            for (int mt = 0; mt < 2; mt++)
                #pragma unroll
                for (int nt = 0; nt < 4; nt++) {
                    float* d = acc[mt][nt];
                    const uint32_t* Bh = &bh[nt >> 1][(nt & 1) * 2];
                    const uint32_t* Bl = &bl[nt >> 1][(nt & 1) * 2];
                    mma16816(d, ah[mt], Bh);   // hi*hi
                    mma16816(d, ah[mt], Bl);   // hi*lo
                    mma16816(d, al[mt], Bh);   // lo*hi
                }
        }
        __syncthreads();
    }

    // Epilogue: bias + optional relu, masked store.
    #pragma unroll
    for (int mt = 0; mt < 2; mt++)
        #pragma unroll
        for (int nt = 0; nt < 4; nt++)
            #pragma unroll
            for (int r = 0; r < 4; r++) {
                int row = blockRow + wm * 32 + mt * 16 + (lane >> 2) + ((r >> 1) ? 8 : 0);
                int col = wn * 32 + nt * 8 + (lane & 3) * 2 + (r & 1);
                if (row < NNODES && col < OCOLS) {
                    float v = acc[mt][nt][r] + bias[col];
                    if (RELU) v = fmaxf(v, 0.0f);
                    out[(size_t)row * OCOLS + col] = v;
                }
            }
}

// ---------------- launcher ---------------------------------------------------
extern "C" void kernel_launch(void* const* d_in, const int* in_sizes, int n_in,
                              void* d_out, int out_size) {
    const float* feats  = (const float*)d_in[0];
    const float* coeff0 = (const float*)d_in[1];
    const float* bases0 = (const float*)d_in[2];
    const float* bias0  = (const float*)d_in[3];
    const float* coeff1 = (const float*)d_in[4];
    const float* bases1 = (const float*)d_in[5];
    const float* bias1  = (const float*)d_in[6];
    const float* coeff2 = (const float*)d_in[7];
    const float* bases2 = (const float*)d_in[8];
    const float* bias2  = (const float*)d_in[9];
    const int*   src    = (const int*)d_in[10];
    const int*   dst    = (const int*)d_in[11];
    const int*   etype  = (const int*)d_in[12];
    const float* norm   = (const float*)d_in[13];
    float* out = (float*)d_out;

    // Graph preprocessing (CSR by dst) + weight conversion
    zero_kernel<<<(NNODES + 255) / 256, 256>>>();
    hist_kernel<<<(NEDGES + 255) / 256, 256>>>(dst);
    scan_kernel<<<1, 1024>>>();
    scatter_kernel<<<(NEDGES + 255) / 256, 256>>>(src, dst, etype, norm);
    wconv_kernel<<<(3 * KDIM * 64 + 255) / 256, 256>>>(bases0, bases1, bases2);

    const int AGG_GRID = NNODES / 8;          // 8 dst-warps per 256-thread block
    const int GEMM_GRID = (NNODES + 127) / 128;

    // Layer 0: feats -> g_h (relu)
    agg_kernel<<<AGG_GRID, 256>>>(feats, coeff0);
    gemm_kernel<true, 64><<<GEMM_GRID, 256>>>(0, bias0, nullptr);

    // Layer 1: g_h -> g_h (relu)
    agg_kernel<<<AGG_GRID, 256>>>(nullptr, coeff1);
    gemm_kernel<true, 64><<<GEMM_GRID, 256>>>(1, bias1, nullptr);

    // Layer 2: g_h -> d_out (no relu, 16 cols)
    agg_kernel<<<AGG_GRID, 256>>>(nullptr, coeff2);
    gemm_kernel<false, 16><<<GEMM_GRID, 256>>>(2, bias2, out);
}